// round 1
// baseline (speedup 1.0000x reference)
#include <cuda_runtime.h>

#define BB 2
#define SS 4096
#define DD 128
#define HALF 64
#define TM 64           // query/row tile per block
#define KU 192          // key union per tile: TM + 2*HALF
#define NT 256          // threads per block

// scratch for Q, K, V (device globals — allocation-free)
__device__ float g_q[BB * SS * DD];
__device__ float g_k[BB * SS * DD];
__device__ float g_v[BB * SS * DD];

// ---------------------------------------------------------------------------
// Kernel 1: QKV projection.  C[m,n] = sum_d X[m,d] * W[d,n] + b[n]
// grid = (B*S)/TM = 128 blocks, 256 threads.
// smem: Xs transposed [D][TM+1] (pad to kill conflicts) + Ws [D][D].
// ---------------------------------------------------------------------------
__global__ __launch_bounds__(NT) void qkv_kernel(
    const float* __restrict__ x,
    const float* __restrict__ Wq, const float* __restrict__ bq,
    const float* __restrict__ Wk, const float* __restrict__ bk,
    const float* __restrict__ Wv, const float* __restrict__ bv)
{
    extern __shared__ float smem[];
    float* Xs = smem;                   // [D][TM+1] : Xs[d*(TM+1)+m]
    float* Ws = smem + DD * (TM + 1);   // [D][D] row-major

    const int tid = threadIdx.x;
    const int m0  = blockIdx.x * TM;

    // load X tile transposed (coalesced global read)
    for (int i = tid; i < TM * DD; i += NT) {
        int m = i / DD, d = i % DD;
        Xs[d * (TM + 1) + m] = x[(m0 + m) * DD + d];
    }

    const float* Wp[3] = {Wq, Wk, Wv};
    const float* bp[3] = {bq, bk, bv};
    float*       op[3] = {g_q, g_k, g_v};

    const int tx = tid & 31;   // n = 4*tx + c
    const int ty = tid >> 5;   // m = ty + 8*r

    for (int w = 0; w < 3; w++) {
        __syncthreads();
        for (int i = tid; i < DD * DD; i += NT) Ws[i] = Wp[w][i];
        __syncthreads();

        float acc[8][4];
        #pragma unroll
        for (int r = 0; r < 8; r++)
            #pragma unroll
            for (int c = 0; c < 4; c++) acc[r][c] = 0.f;

        #pragma unroll 4
        for (int d = 0; d < DD; d++) {
            float4 wv = *(const float4*)&Ws[d * DD + 4 * tx];
            #pragma unroll
            for (int r = 0; r < 8; r++) {
                float xv = Xs[d * (TM + 1) + ty + 8 * r];  // broadcast in warp
                acc[r][0] += xv * wv.x;
                acc[r][1] += xv * wv.y;
                acc[r][2] += xv * wv.z;
                acc[r][3] += xv * wv.w;
            }
        }

        float4 bias = *(const float4*)&bp[w][4 * tx];
        #pragma unroll
        for (int r = 0; r < 8; r++) {
            float4 o;
            o.x = acc[r][0] + bias.x;
            o.y = acc[r][1] + bias.y;
            o.z = acc[r][2] + bias.z;
            o.w = acc[r][3] + bias.w;
            *(float4*)&op[w][(m0 + ty + 8 * r) * DD + 4 * tx] = o;
        }
    }
}

// ---------------------------------------------------------------------------
// Kernel 2: sliding-window attention over a TM=64 query tile.
// grid = B * (S/TM) = 128 blocks (one wave), 256 threads.
// smem: KV buffer (K transposed, later reused for V), Qt transposed, scores.
// ---------------------------------------------------------------------------
#define KT_PITCH 193            // Kt[d*193 + j], pad kills conflicts
#define QT_PITCH (TM + 1)       // Qt[d*65 + q]
#define SC_PITCH 193            // Sc[q*193 + j]
#define KV_WORDS (DD * KT_PITCH)        // 24704 (>= 192*128 for V reuse)
#define QT_WORDS (DD * QT_PITCH)        // 8320
#define SC_WORDS (TM * SC_PITCH)        // 12352
#define ATTN_SMEM_BYTES ((KV_WORDS + QT_WORDS + SC_WORDS) * 4)   // 181504

__global__ __launch_bounds__(NT) void attn_kernel(float* __restrict__ out)
{
    extern __shared__ float smem[];
    float* KV = smem;                       // Kt phase: [D][193]; V phase: [192][128]
    float* Qt = smem + KV_WORDS;            // [D][65]
    float* Sc = smem + KV_WORDS + QT_WORDS; // [64][193]

    const int tid = threadIdx.x;
    const int b   = blockIdx.x >> 6;        // 64 tiles per batch
    const int q0  = (blockIdx.x & 63) * TM;
    const int kb  = q0 - HALF;              // key window base (may be <0)

    const float* qg = g_q + b * SS * DD;
    const float* kg = g_k + b * SS * DD;
    const float* vg = g_v + b * SS * DD;

    // load Q tile transposed
    for (int i = tid; i < TM * DD; i += NT) {
        int m = i / DD, d = i % DD;
        Qt[d * QT_PITCH + m] = qg[(q0 + m) * DD + d];
    }
    // load K union transposed (zero-fill out-of-range rows)
    for (int i = tid; i < KU * DD; i += NT) {
        int j = i / DD, d = i % DD;
        int key = kb + j;
        KV[d * KT_PITCH + j] = (key >= 0 && key < SS) ? kg[key * DD + d] : 0.f;
    }
    __syncthreads();

    const int tx = tid & 31;   // j = tx + 32*u
    const int ty = tid >> 5;   // q = ty + 8*r

    // ---- phase A: S = Q @ K^T over the union ----
    float acc[8][6];
    #pragma unroll
    for (int r = 0; r < 8; r++)
        #pragma unroll
        for (int u = 0; u < 6; u++) acc[r][u] = 0.f;

    #pragma unroll 2
    for (int d = 0; d < DD; d++) {
        float kv[6], qv[8];
        #pragma unroll
        for (int u = 0; u < 6; u++) kv[u] = KV[d * KT_PITCH + tx + 32 * u];
        #pragma unroll
        for (int r = 0; r < 8; r++) qv[r] = Qt[d * QT_PITCH + ty + 8 * r];
        #pragma unroll
        for (int r = 0; r < 8; r++)
            #pragma unroll
            for (int u = 0; u < 6; u++) acc[r][u] += qv[r] * kv[u];
    }

    const float scale = 0.088388347648318447f;  // 1/sqrt(128)
    #pragma unroll
    for (int r = 0; r < 8; r++) {
        int qi = ty + 8 * r;
        #pragma unroll
        for (int u = 0; u < 6; u++) {
            int j   = tx + 32 * u;
            int key = kb + j;
            int dj  = j - qi;                     // in [0,128] iff |key - q| <= 64
            bool valid = (key >= 0) && (key < SS) && (dj >= 0) && (dj <= 2 * HALF);
            Sc[qi * SC_PITCH + j] = valid ? acc[r][u] * scale : -1e30f;
        }
    }
    __syncthreads();

    // ---- load V over the KV buffer (K reads are done) ----
    for (int i = tid; i < KU * DD; i += NT) {
        int j = i / DD, d = i % DD;
        int key = kb + j;
        KV[j * DD + d] = (key >= 0 && key < SS) ? vg[key * DD + d] : 0.f;
    }

    // ---- softmax: 4 threads per row ----
    {
        int row = tid >> 2, sub = tid & 3;
        float m = -1e30f;
        for (int j = sub; j < KU; j += 4) m = fmaxf(m, Sc[row * SC_PITCH + j]);
        m = fmaxf(m, __shfl_xor_sync(0xffffffffu, m, 1));
        m = fmaxf(m, __shfl_xor_sync(0xffffffffu, m, 2));
        float sum = 0.f;
        for (int j = sub; j < KU; j += 4) {
            float s = Sc[row * SC_PITCH + j];
            float p = (s < -1e29f) ? 0.f : __expf(s - m);
            Sc[row * SC_PITCH + j] = p;
            sum += p;
        }
        sum += __shfl_xor_sync(0xffffffffu, sum, 1);
        sum += __shfl_xor_sync(0xffffffffu, sum, 2);
        float inv = 1.f / sum;
        for (int j = sub; j < KU; j += 4) Sc[row * SC_PITCH + j] *= inv;
    }
    __syncthreads();

    // ---- phase C: O = P @ V ----
    float oacc[8][4];
    #pragma unroll
    for (int r = 0; r < 8; r++)
        #pragma unroll
        for (int c = 0; c < 4; c++) oacc[r][c] = 0.f;

    #pragma unroll 2
    for (int j = 0; j < KU; j++) {
        float4 vv = *(const float4*)&KV[j * DD + 4 * tx];
        #pragma unroll
        for (int r = 0; r < 8; r++) {
            float p = Sc[(ty + 8 * r) * SC_PITCH + j];   // warp broadcast
            oacc[r][0] += p * vv.x;
            oacc[r][1] += p * vv.y;
            oacc[r][2] += p * vv.z;
            oacc[r][3] += p * vv.w;
        }
    }

    #pragma unroll
    for (int r = 0; r < 8; r++) {
        int qi = ty + 8 * r;
        float4 o = make_float4(oacc[r][0], oacc[r][1], oacc[r][2], oacc[r][3]);
        *(float4*)&out[((b * SS) + q0 + qi) * DD + 4 * tx] = o;
    }
}

// ---------------------------------------------------------------------------
extern "C" void kernel_launch(void* const* d_in, const int* in_sizes, int n_in,
                              void* d_out, int out_size)
{
    const float* x  = (const float*)d_in[0];
    const float* Wq = (const float*)d_in[1];
    const float* bq = (const float*)d_in[2];
    const float* Wk = (const float*)d_in[3];
    const float* bk = (const float*)d_in[4];
    const float* Wv = (const float*)d_in[5];
    const float* bv = (const float*)d_in[6];
    float* out = (float*)d_out;

    const int qkv_smem = (DD * (TM + 1) + DD * DD) * 4;   // 98816 B
    cudaFuncSetAttribute(qkv_kernel, cudaFuncAttributeMaxDynamicSharedMemorySize, qkv_smem);
    cudaFuncSetAttribute(attn_kernel, cudaFuncAttributeMaxDynamicSharedMemorySize, ATTN_SMEM_BYTES);

    qkv_kernel<<<(BB * SS) / TM, NT, qkv_smem>>>(x, Wq, bq, Wk, bk, Wv, bv);
    attn_kernel<<<BB * (SS / TM), NT, ATTN_SMEM_BYTES>>>(out);
}

// round 6
// speedup vs baseline: 1.0503x; 1.0503x over previous
#include <cuda_runtime.h>
#include <cstdint>

#define BB 2
#define SS 4096
#define DD 128
#define HALF 64
#define TM 64            // rows per CTA (both kernels)
#define KU 192           // key union per tile
#define NT 256           // 8 warps

// Q/K/V scratch (device globals — allocation-free)
__device__ float g_q[BB * SS * DD];
__device__ float g_k[BB * SS * DD];
__device__ float g_v[BB * SS * DD];

__device__ __forceinline__ uint32_t f2tf32(float f) {
    uint32_t u;
    asm("cvt.rna.tf32.f32 %0, %1;" : "=r"(u) : "f"(f));
    return u;
}

// D += A*B  (m16n8k8, tf32, row.col)
__device__ __forceinline__ void mma8(float* c, const uint32_t* a, uint32_t b0, uint32_t b1) {
    asm volatile(
        "mma.sync.aligned.m16n8k8.row.col.f32.tf32.tf32.f32 "
        "{%0,%1,%2,%3}, {%4,%5,%6,%7}, {%8,%9}, {%0,%1,%2,%3};"
        : "+f"(c[0]), "+f"(c[1]), "+f"(c[2]), "+f"(c[3])
        : "r"(a[0]), "r"(a[1]), "r"(a[2]), "r"(a[3]), "r"(b0), "r"(b1));
}

// smem pitches (in 4B words), chosen for conflict-free fragment loads:
//  A-pattern (addr = row*P + col, row=lane/4, col=lane%4):  P%32==4  -> 132, 196
//  B-pattern (addr = k*P + n,   k=lane%4,  n=lane/4):       P%32==8  -> 136
#define XP 132
#define WP 136
#define PP 196

// ---------------------------------------------------------------------------
// Kernel 1: QKV projection. grid=128, 256 threads.
// ---------------------------------------------------------------------------
#define QKV_SMEM ((TM * XP + DD * WP) * 4)

__global__ __launch_bounds__(NT, 1) void qkv_kernel(
    const float* __restrict__ x,
    const float* __restrict__ Wq, const float* __restrict__ bq,
    const float* __restrict__ Wk, const float* __restrict__ bk,
    const float* __restrict__ Wv, const float* __restrict__ bv)
{
    extern __shared__ uint32_t smem[];
    uint32_t* Xs = smem;            // [64][XP]  tf32 bits
    uint32_t* Ws = smem + TM * XP;  // [128][WP] tf32 bits

    const int tid = threadIdx.x, w = tid >> 5, lane = tid & 31;
    const int gy = lane >> 2, gx = lane & 3;
    const int m0 = blockIdx.x * TM;

    for (int i = tid; i < TM * DD; i += NT) {
        int m = i >> 7, d = i & 127;
        Xs[m * XP + d] = f2tf32(x[(m0 + m) * DD + d]);
    }

    const float* Wg[3] = {Wq, Wk, Wv};
    const float* bg[3] = {bq, bk, bv};
    float*       og[3] = {g_q, g_k, g_v};

    const int r0 = 16 * (w & 3);        // warp row base
    const int c0 = 64 * (w >> 2);       // warp col base

    for (int wi = 0; wi < 3; wi++) {
        __syncthreads();
        for (int i = tid; i < DD * DD; i += NT) {
            int d = i >> 7, n = i & 127;
            Ws[d * WP + n] = f2tf32(Wg[wi][i]);
        }
        __syncthreads();

        float acc[8][4];
        #pragma unroll
        for (int t = 0; t < 8; t++)
            #pragma unroll
            for (int c = 0; c < 4; c++) acc[t][c] = 0.f;

        #pragma unroll
        for (int ks = 0; ks < 16; ks++) {
            const int k0 = 8 * ks;
            uint32_t a[4];
            a[0] = Xs[(r0 + gy) * XP + k0 + gx];
            a[1] = Xs[(r0 + gy + 8) * XP + k0 + gx];
            a[2] = Xs[(r0 + gy) * XP + k0 + gx + 4];
            a[3] = Xs[(r0 + gy + 8) * XP + k0 + gx + 4];
            #pragma unroll
            for (int t = 0; t < 8; t++) {
                int n0 = c0 + 8 * t;
                uint32_t b0 = Ws[(k0 + gx) * WP + n0 + gy];
                uint32_t b1 = Ws[(k0 + gx + 4) * WP + n0 + gy];
                mma8(acc[t], a, b0, b1);
            }
        }

        #pragma unroll
        for (int t = 0; t < 8; t++) {
            int col = c0 + 8 * t + 2 * gx;
            float bx = bg[wi][col], by = bg[wi][col + 1];
            float2 v0 = make_float2(acc[t][0] + bx, acc[t][1] + by);
            float2 v1 = make_float2(acc[t][2] + bx, acc[t][3] + by);
            *(float2*)&og[wi][(m0 + r0 + gy) * DD + col]     = v0;
            *(float2*)&og[wi][(m0 + r0 + gy + 8) * DD + col] = v1;
        }
    }
}

// ---------------------------------------------------------------------------
// Kernel 2: sliding-window attention. grid=128, 256 threads.
// smem: Qs [64][XP], KV (K:[192][XP] then V:[192][WP]), Ps [64][PP]
// ---------------------------------------------------------------------------
#define KV_WORDS (KU * WP)                   // max of the two phases
#define ATTN_SMEM ((TM * XP + KV_WORDS + TM * PP) * 4)

__global__ __launch_bounds__(NT, 1) void attn_kernel(float* __restrict__ out)
{
    extern __shared__ uint32_t smem[];
    uint32_t* Qs = smem;                        // [64][XP]
    uint32_t* KV = smem + TM * XP;              // K: [192][XP] / V: [192][WP]
    float*    Ps = (float*)(smem + TM * XP + KV_WORDS);  // [64][PP]

    const int tid = threadIdx.x, w = tid >> 5, lane = tid & 31;
    const int gy = lane >> 2, gx = lane & 3;
    const int b  = blockIdx.x >> 6;
    const int q0 = (blockIdx.x & 63) * TM;
    const int kb = q0 - HALF;

    const float scale = 0.088388347648318447f;  // 1/sqrt(128)
    const float* qg = g_q + b * SS * DD;
    const float* kg = g_k + b * SS * DD;
    const float* vg = g_v + b * SS * DD;

    for (int i = tid; i < TM * DD; i += NT) {
        int m = i >> 7, d = i & 127;
        Qs[m * XP + d] = f2tf32(qg[(q0 + m) * DD + d] * scale);
    }
    for (int i = tid; i < KU * DD; i += NT) {
        int j = i >> 7, d = i & 127;
        int key = kb + j;
        float v = (key >= 0 && key < SS) ? kg[key * DD + d] : 0.f;
        KV[j * XP + d] = f2tf32(v);
    }
    __syncthreads();

    // ---- S = Q @ K^T : warp = m16 x n96 (12 tiles) ----
    const int r0 = 16 * (w & 3);
    const int cb = 96 * (w >> 2);
    {
        float sacc[12][4];
        #pragma unroll
        for (int t = 0; t < 12; t++)
            #pragma unroll
            for (int c = 0; c < 4; c++) sacc[t][c] = 0.f;

        #pragma unroll
        for (int ks = 0; ks < 16; ks++) {
            const int k0 = 8 * ks;
            uint32_t a[4];
            a[0] = Qs[(r0 + gy) * XP + k0 + gx];
            a[1] = Qs[(r0 + gy + 8) * XP + k0 + gx];
            a[2] = Qs[(r0 + gy) * XP + k0 + gx + 4];
            a[3] = Qs[(r0 + gy + 8) * XP + k0 + gx + 4];
            #pragma unroll
            for (int t = 0; t < 12; t++) {
                int n0 = cb + 8 * t;
                uint32_t b0 = KV[(n0 + gy) * XP + k0 + gx];
                uint32_t b1 = KV[(n0 + gy) * XP + k0 + gx + 4];
                mma8(sacc[t], a, b0, b1);
            }
        }

        // write scores with band mask (valid iff 0 <= j - q <= 128 and key in range)
        #pragma unroll
        for (int t = 0; t < 12; t++) {
            #pragma unroll
            for (int h = 0; h < 2; h++) {
                int q = r0 + gy + 8 * h;
                #pragma unroll
                for (int cc = 0; cc < 2; cc++) {
                    int j   = cb + 8 * t + 2 * gx + cc;
                    int key = kb + j;
                    int dj  = j - q;
                    bool valid = (dj >= 0) && (dj <= 2 * HALF) && (key >= 0) && (key < SS);
                    Ps[q * PP + j] = valid ? sacc[t][2 * h + cc] : -1e30f;
                }
            }
        }
    }
    __syncthreads();

    // ---- V overwrites K buffer (pitch WP) ----
    for (int i = tid; i < KU * DD; i += NT) {
        int j = i >> 7, d = i & 127;
        int key = kb + j;
        float v = (key >= 0 && key < SS) ? vg[key * DD + d] : 0.f;
        KV[j * WP + d] = f2tf32(v);
    }

    // ---- softmax: 4 threads per row; final pass stores tf32 bits ----
    {
        int row = tid >> 2, sub = tid & 3;
        float m = -1e30f;
        for (int j = sub; j < KU; j += 4) m = fmaxf(m, Ps[row * PP + j]);
        m = fmaxf(m, __shfl_xor_sync(0xffffffffu, m, 1));
        m = fmaxf(m, __shfl_xor_sync(0xffffffffu, m, 2));
        float sum = 0.f;
        for (int j = sub; j < KU; j += 4) {
            float s = Ps[row * PP + j];
            float p = (s < -1e29f) ? 0.f : __expf(s - m);
            Ps[row * PP + j] = p;
            sum += p;
        }
        sum += __shfl_xor_sync(0xffffffffu, sum, 1);
        sum += __shfl_xor_sync(0xffffffffu, sum, 2);
        float inv = 1.f / sum;
        for (int j = sub; j < KU; j += 4)
            ((uint32_t*)Ps)[row * PP + j] = f2tf32(Ps[row * PP + j] * inv);
    }
    __syncthreads();

    // ---- O = P @ V : warp = m16 x n64 (8 tiles), 24 k-steps ----
    {
        const int d0 = 64 * (w >> 2);
        float oacc[8][4];
        #pragma unroll
        for (int t = 0; t < 8; t++)
            #pragma unroll
            for (int c = 0; c < 4; c++) oacc[t][c] = 0.f;

        const uint32_t* Pu = (const uint32_t*)Ps;
        #pragma unroll
        for (int ks = 0; ks < 24; ks++) {
            const int k0 = 8 * ks;
            uint32_t a[4];
            a[0] = Pu[(r0 + gy) * PP + k0 + gx];
            a[1] = Pu[(r0 + gy + 8) * PP + k0 + gx];
            a[2] = Pu[(r0 + gy) * PP + k0 + gx + 4];
            a[3] = Pu[(r0 + gy + 8) * PP + k0 + gx + 4];
            #pragma unroll
            for (int t = 0; t < 8; t++) {
                int n0 = d0 + 8 * t;
                uint32_t b0 = KV[(k0 + gx) * WP + n0 + gy];
                uint32_t b1 = KV[(k0 + gx + 4) * WP + n0 + gy];
                mma8(oacc[t], a, b0, b1);
            }
        }

        float* ob = out + (size_t)(b * SS + q0) * DD;
        #pragma unroll
        for (int t = 0; t < 8; t++) {
            int col = d0 + 8 * t + 2 * gx;
            *(float2*)&ob[(r0 + gy) * DD + col]     = make_float2(oacc[t][0], oacc[t][1]);
            *(float2*)&ob[(r0 + gy + 8) * DD + col] = make_float2(oacc[t][2], oacc[t][3]);
        }
    }
}

// ---------------------------------------------------------------------------
extern "C" void kernel_launch(void* const* d_in, const int* in_sizes, int n_in,
                              void* d_out, int out_size)
{
    const float* x  = (const float*)d_in[0];
    const float* Wq = (const float*)d_in[1];
    const float* bq = (const float*)d_in[2];
    const float* Wk = (const float*)d_in[3];
    const float* bk = (const float*)d_in[4];
    const float* Wv = (const float*)d_in[5];
    const float* bv = (const float*)d_in[6];
    float* out = (float*)d_out;

    cudaFuncSetAttribute(qkv_kernel,  cudaFuncAttributeMaxDynamicSharedMemorySize, QKV_SMEM);
    cudaFuncSetAttribute(attn_kernel, cudaFuncAttributeMaxDynamicSharedMemorySize, ATTN_SMEM);

    qkv_kernel<<<(BB * SS) / TM, NT, QKV_SMEM>>>(x, Wq, bq, Wk, bk, Wv, bv);
    attn_kernel<<<BB * (SS / TM), NT, ATTN_SMEM>>>(out);
}

// round 7
// speedup vs baseline: 3.0606x; 2.9141x over previous
#include <cuda_runtime.h>
#include <cstdint>

#define BB 2
#define SS 4096
#define DD 128
#define HALF 64
#define TM 64            // rows per CTA (both kernels)
#define KU 192           // key union per tile
#define NT 256           // 8 warps

// Q/K/V scratch as tf32 bit patterns (Q pre-scaled by 1/sqrt(D))
__device__ uint32_t g_q[BB * SS * DD];
__device__ uint32_t g_k[BB * SS * DD];
__device__ uint32_t g_v[BB * SS * DD];

__device__ __forceinline__ uint32_t f2tf32(float f) {
    uint32_t u;
    asm("cvt.rna.tf32.f32 %0, %1;" : "=r"(u) : "f"(f));
    return u;
}
__device__ __forceinline__ uint32_t smem_u32(const void* p) {
    uint32_t a;
    asm("{ .reg .u64 t; cvta.to.shared.u64 t, %1; cvt.u32.u64 %0, t; }" : "=r"(a) : "l"(p));
    return a;
}
// 16B async copy, src_size<16 zero-fills
__device__ __forceinline__ void cpa(uint32_t dst, const void* src, int srcsz) {
    asm volatile("cp.async.cg.shared.global [%0], [%1], 16, %2;"
                 :: "r"(dst), "l"(src), "r"(srcsz) : "memory");
}
#define CP_COMMIT() asm volatile("cp.async.commit_group;" ::: "memory")
#define CP_WAIT(n)  asm volatile("cp.async.wait_group %0;" :: "n"(n) : "memory")

// D += A*B  (m16n8k8, tf32, row.col)
__device__ __forceinline__ void mma8(float* c, const uint32_t* a, uint32_t b0, uint32_t b1) {
    asm volatile(
        "mma.sync.aligned.m16n8k8.row.col.f32.tf32.tf32.f32 "
        "{%0,%1,%2,%3}, {%4,%5,%6,%7}, {%8,%9}, {%0,%1,%2,%3};"
        : "+f"(c[0]), "+f"(c[1]), "+f"(c[2]), "+f"(c[3])
        : "r"(a[0]), "r"(a[1]), "r"(a[2]), "r"(a[3]), "r"(b0), "r"(b1));
}

// smem pitches (words): A-pattern pitch%32==4 (132,196), B-pattern pitch%32==8 (136)
#define XP 132
#define WP 136
#define PP 196

// ---------------------------------------------------------------------------
// Kernel 1: QKV projection, W double-buffered via cp.async. grid=128.
// ---------------------------------------------------------------------------
#define QXS_W (TM * XP)       // 8448
#define QWS_W (DD * WP)       // 17408
#define QKV_SMEM ((QXS_W + 2 * QWS_W) * 4)   // 173056

__global__ __launch_bounds__(NT, 1) void qkv_kernel(
    const float* __restrict__ x,
    const float* __restrict__ Wq, const float* __restrict__ bq,
    const float* __restrict__ Wk, const float* __restrict__ bk,
    const float* __restrict__ Wv, const float* __restrict__ bv)
{
    extern __shared__ uint32_t smem[];
    const float* Xs  = (const float*)smem;
    const float* WsA = (const float*)(smem + QXS_W);
    const float* WsB = WsA + QWS_W;

    const uint32_t sb   = smem_u32(smem);
    const uint32_t xs_b = sb;
    const uint32_t wsA  = sb + QXS_W * 4;
    const uint32_t wsB  = wsA + QWS_W * 4;

    const int tid = threadIdx.x, w = tid >> 5, lane = tid & 31;
    const int gy = lane >> 2, gx = lane & 3;
    const int m0 = blockIdx.x * TM;
    const int r0 = 16 * (w & 3);
    const int c0 = 64 * (w >> 2);

    // group0: X + Wq ; group1: Wk
    for (int i = tid; i < TM * 32; i += NT) {
        int m = i >> 5, c = (i & 31) << 2;
        cpa(xs_b + (uint32_t)(m * XP + c) * 4, &x[(m0 + m) * DD + c], 16);
    }
    for (int i = tid; i < DD * 32; i += NT) {
        int d = i >> 5, c = (i & 31) << 2;
        cpa(wsA + (uint32_t)(d * WP + c) * 4, &Wq[d * DD + c], 16);
    }
    CP_COMMIT();
    for (int i = tid; i < DD * 32; i += NT) {
        int d = i >> 5, c = (i & 31) << 2;
        cpa(wsB + (uint32_t)(d * WP + c) * 4, &Wk[d * DD + c], 16);
    }
    CP_COMMIT();
    CP_WAIT(1);
    __syncthreads();

    const float scale = 0.088388347648318447f;  // 1/sqrt(128)

    auto run_mma = [&](const float* Wf, float acc[8][4]) {
        #pragma unroll
        for (int t = 0; t < 8; t++)
            #pragma unroll
            for (int c = 0; c < 4; c++) acc[t][c] = 0.f;
        #pragma unroll
        for (int ks = 0; ks < 16; ks++) {
            const int k0 = 8 * ks;
            uint32_t a[4];
            a[0] = f2tf32(Xs[(r0 + gy) * XP + k0 + gx]);
            a[1] = f2tf32(Xs[(r0 + gy + 8) * XP + k0 + gx]);
            a[2] = f2tf32(Xs[(r0 + gy) * XP + k0 + gx + 4]);
            a[3] = f2tf32(Xs[(r0 + gy + 8) * XP + k0 + gx + 4]);
            #pragma unroll
            for (int t = 0; t < 8; t++) {
                int n0 = c0 + 8 * t;
                uint32_t b0 = f2tf32(Wf[(k0 + gx) * WP + n0 + gy]);
                uint32_t b1 = f2tf32(Wf[(k0 + gx + 4) * WP + n0 + gy]);
                mma8(acc[t], a, b0, b1);
            }
        }
    };
    auto store_r = [&](uint32_t* dst, const float* bias, float scl, float acc[8][4]) {
        #pragma unroll
        for (int t = 0; t < 8; t++) {
            int col = c0 + 8 * t + 2 * gx;
            float bx = bias[col], by = bias[col + 1];
            uint2 v0 = make_uint2(f2tf32((acc[t][0] + bx) * scl), f2tf32((acc[t][1] + by) * scl));
            uint2 v1 = make_uint2(f2tf32((acc[t][2] + bx) * scl), f2tf32((acc[t][3] + by) * scl));
            *(uint2*)&dst[(size_t)(m0 + r0 + gy) * DD + col]     = v0;
            *(uint2*)&dst[(size_t)(m0 + r0 + gy + 8) * DD + col] = v1;
        }
    };

    float acc[8][4];
    run_mma(WsA, acc);               // Q (Wk streaming in behind)
    store_r(g_q, bq, scale, acc);

    CP_WAIT(0);                      // Wk ready
    __syncthreads();                 // all warps done reading WsA
    for (int i = tid; i < DD * 32; i += NT) {
        int d = i >> 5, c = (i & 31) << 2;
        cpa(wsA + (uint32_t)(d * WP + c) * 4, &Wv[d * DD + c], 16);
    }
    CP_COMMIT();

    run_mma(WsB, acc);               // K (Wv streaming in behind)
    store_r(g_k, bk, 1.f, acc);

    CP_WAIT(0);
    __syncthreads();

    run_mma(WsA, acc);               // V
    store_r(g_v, bv, 1.f, acc);
}

// ---------------------------------------------------------------------------
// Kernel 2: sliding-window attention. grid=128. V copy overlapped w/ softmax.
// ---------------------------------------------------------------------------
#define AQS_W (TM * XP)       // 8448
#define AKV_W (KU * WP)       // 26112 (holds K at pitch XP, then V at pitch WP)
#define APS_W (TM * PP)       // 12544
#define ATTN_SMEM ((AQS_W + AKV_W + APS_W) * 4)   // 188416

__global__ __launch_bounds__(NT, 1) void attn_kernel(float* __restrict__ out)
{
    extern __shared__ uint32_t smem[];
    const uint32_t* Qs = smem;                    // [64][XP] tf32 bits
    const uint32_t* KV = smem + AQS_W;            // K:[192][XP] / V:[192][WP]
    float*          Ps = (float*)(smem + AQS_W + AKV_W);  // [64][PP]

    const uint32_t sb   = smem_u32(smem);
    const uint32_t qs_b = sb;
    const uint32_t kv_b = sb + AQS_W * 4;

    const int tid = threadIdx.x, w = tid >> 5, lane = tid & 31;
    const int gy = lane >> 2, gx = lane & 3;
    const int b  = blockIdx.x >> 6;
    const int q0 = (blockIdx.x & 63) * TM;
    const int kb = q0 - HALF;

    const uint32_t* qg = g_q + (size_t)b * SS * DD;
    const uint32_t* kg = g_k + (size_t)b * SS * DD;
    const uint32_t* vg = g_v + (size_t)b * SS * DD;

    // stage Q + K (zero-fill OOB rows)
    for (int i = tid; i < TM * 32; i += NT) {
        int m = i >> 5, c = (i & 31) << 2;
        cpa(qs_b + (uint32_t)(m * XP + c) * 4, &qg[(q0 + m) * DD + c], 16);
    }
    for (int i = tid; i < KU * 32; i += NT) {
        int j = i >> 5, c = (i & 31) << 2;
        int key = kb + j;
        int ok = (key >= 0 && key < SS);
        cpa(kv_b + (uint32_t)(j * XP + c) * 4, &kg[(size_t)(ok ? key : 0) * DD + c], ok ? 16 : 0);
    }
    CP_COMMIT();
    CP_WAIT(0);
    __syncthreads();

    // ---- S = Q @ K^T : warp = m16 x n96 ----
    const int r0 = 16 * (w & 3);
    const int cb = 96 * (w >> 2);
    {
        float sacc[12][4];
        #pragma unroll
        for (int t = 0; t < 12; t++)
            #pragma unroll
            for (int c = 0; c < 4; c++) sacc[t][c] = 0.f;

        #pragma unroll
        for (int ks = 0; ks < 16; ks++) {
            const int k0 = 8 * ks;
            uint32_t a[4];
            a[0] = Qs[(r0 + gy) * XP + k0 + gx];
            a[1] = Qs[(r0 + gy + 8) * XP + k0 + gx];
            a[2] = Qs[(r0 + gy) * XP + k0 + gx + 4];
            a[3] = Qs[(r0 + gy + 8) * XP + k0 + gx + 4];
            #pragma unroll
            for (int t = 0; t < 12; t++) {
                int n0 = cb + 8 * t;
                uint32_t b0 = KV[(n0 + gy) * XP + k0 + gx];
                uint32_t b1 = KV[(n0 + gy) * XP + k0 + gx + 4];
                mma8(sacc[t], a, b0, b1);
            }
        }

        #pragma unroll
        for (int t = 0; t < 12; t++) {
            #pragma unroll
            for (int h = 0; h < 2; h++) {
                int q = r0 + gy + 8 * h;
                #pragma unroll
                for (int cc = 0; cc < 2; cc++) {
                    int j   = cb + 8 * t + 2 * gx + cc;
                    int key = kb + j;
                    int dj  = j - q;
                    bool valid = (dj >= 0) && (dj <= 2 * HALF) && (key >= 0) && (key < SS);
                    Ps[q * PP + j] = valid ? sacc[t][2 * h + cc] : -1e30f;
                }
            }
        }
    }
    __syncthreads();          // all MMA1 reads of KV done; Ps complete

    // ---- fire V copy (overlaps the whole softmax) ----
    for (int i = tid; i < KU * 32; i += NT) {
        int j = i >> 5, c = (i & 31) << 2;
        int key = kb + j;
        int ok = (key >= 0 && key < SS);
        cpa(kv_b + (uint32_t)(j * WP + c) * 4, &vg[(size_t)(ok ? key : 0) * DD + c], ok ? 16 : 0);
    }
    CP_COMMIT();

    // ---- softmax: 4 threads per row; final pass stores tf32 bits ----
    {
        int row = tid >> 2, sub = tid & 3;
        float m = -1e30f;
        for (int j = sub; j < KU; j += 4) m = fmaxf(m, Ps[row * PP + j]);
        m = fmaxf(m, __shfl_xor_sync(0xffffffffu, m, 1));
        m = fmaxf(m, __shfl_xor_sync(0xffffffffu, m, 2));
        float sum = 0.f;
        for (int j = sub; j < KU; j += 4) {
            float s = Ps[row * PP + j];
            float p = (s < -1e29f) ? 0.f : __expf(s - m);
            Ps[row * PP + j] = p;
            sum += p;
        }
        sum += __shfl_xor_sync(0xffffffffu, sum, 1);
        sum += __shfl_xor_sync(0xffffffffu, sum, 2);
        float inv = 1.f / sum;
        for (int j = sub; j < KU; j += 4)
            ((uint32_t*)Ps)[row * PP + j] = f2tf32(Ps[row * PP + j] * inv);
    }
    CP_WAIT(0);
    __syncthreads();

    // ---- O = P @ V : warp = m16 x n64, 24 k-steps ----
    {
        const int d0 = 64 * (w >> 2);
        float oacc[8][4];
        #pragma unroll
        for (int t = 0; t < 8; t++)
            #pragma unroll
            for (int c = 0; c < 4; c++) oacc[t][c] = 0.f;

        const uint32_t* Pu = (const uint32_t*)Ps;
        #pragma unroll
        for (int ks = 0; ks < 24; ks++) {
            const int k0 = 8 * ks;
            uint32_t a[4];
            a[0] = Pu[(r0 + gy) * PP + k0 + gx];
            a[1] = Pu[(r0 + gy + 8) * PP + k0 + gx];
            a[2] = Pu[(r0 + gy) * PP + k0 + gx + 4];
            a[3] = Pu[(r0 + gy + 8) * PP + k0 + gx + 4];
            #pragma unroll
            for (int t = 0; t < 8; t++) {
                int n0 = d0 + 8 * t;
                uint32_t b0 = KV[(k0 + gx) * WP + n0 + gy];
                uint32_t b1 = KV[(k0 + gx + 4) * WP + n0 + gy];
                mma8(oacc[t], a, b0, b1);
            }
        }

        float* ob = out + (size_t)(b * SS + q0) * DD;
        #pragma unroll
        for (int t = 0; t < 8; t++) {
            int col = d0 + 8 * t + 2 * gx;
            *(float2*)&ob[(r0 + gy) * DD + col]     = make_float2(oacc[t][0], oacc[t][1]);
            *(float2*)&ob[(r0 + gy + 8) * DD + col] = make_float2(oacc[t][2], oacc[t][3]);
        }
    }
}

// ---------------------------------------------------------------------------
extern "C" void kernel_launch(void* const* d_in, const int* in_sizes, int n_in,
                              void* d_out, int out_size)
{
    const float* x  = (const float*)d_in[0];
    const float* Wq = (const float*)d_in[1];
    const float* bq = (const float*)d_in[2];
    const float* Wk = (const float*)d_in[3];
    const float* bk = (const float*)d_in[4];
    const float* Wv = (const float*)d_in[5];
    const float* bv = (const float*)d_in[6];
    float* out = (float*)d_out;

    cudaFuncSetAttribute(qkv_kernel,  cudaFuncAttributeMaxDynamicSharedMemorySize, QKV_SMEM);
    cudaFuncSetAttribute(attn_kernel, cudaFuncAttributeMaxDynamicSharedMemorySize, ATTN_SMEM);

    qkv_kernel<<<(BB * SS) / TM, NT, QKV_SMEM>>>(x, Wq, bq, Wk, bk, Wv, bv);
    attn_kernel<<<BB * (SS / TM), NT, ATTN_SMEM>>>(out);
}